// round 14
// baseline (speedup 1.0000x reference)
#include <cuda_runtime.h>

#define BATCH 16
#define SEQ   8192
#define BL    (BATCH*SEQ)      // 131072 tokens
#define DM    64
#define DI    128
#define DS    16
#define CH    128              // scan chunk length
#define NCHUNK (SEQ/CH)        // 64

typedef unsigned long long u64;

// ---------------- scratch (device globals; no runtime allocation) ----------
__device__ float  g_xin[BL*DM];
__device__ float  g_xc [BL*DI];
__device__ float  g_sz [BL*DI];          // silu(z)
__device__ float2 g_ed [BL*DI];          // (E, dt*u)
__device__ float  g_uu [BL*DI];          // u * D_skip
__device__ float  g_Bm [BL*DS];
__device__ float  g_Cm [BL*DS];
__device__ float  g_yg [BL*DI];          // raw scan output y
__device__ float  g_Wcat[64*320];
__device__ float  g_bcat[320];
__device__ float  g_sd  [BATCH*NCHUNK*DI];          // sum of dt per chunk
__device__ float  g_Hend[BATCH*NCHUNK*DI*DS];
__device__ float  g_hini[BATCH*NCHUNK*DI*DS];
__device__ float  g_dummy;

// ---------------- packed f32x2 helpers -------------------------------------
__device__ __forceinline__ u64 pk2(float lo, float hi){
    u64 r; asm("mov.b64 %0,{%1,%2};" : "=l"(r) : "f"(lo), "f"(hi)); return r;
}
__device__ __forceinline__ void up2(u64 p, float &lo, float &hi){
    asm("mov.b64 {%0,%1},%2;" : "=f"(lo), "=f"(hi) : "l"(p));
}
__device__ __forceinline__ u64 fma2(u64 a, u64 b, u64 c){
    u64 d; asm("fma.rn.f32x2 %0,%1,%2,%3;" : "=l"(d) : "l"(a), "l"(b), "l"(c)); return d;
}
__device__ __forceinline__ u64 mul2(u64 a, u64 b){
    u64 d; asm("mul.rn.f32x2 %0,%1,%2;" : "=l"(d) : "l"(a), "l"(b)); return d;
}
__device__ __forceinline__ u64 f4lo(float4 v){ return pk2(v.x, v.y); }
__device__ __forceinline__ u64 f4hi(float4 v){ return pk2(v.z, v.w); }
__device__ __forceinline__ unsigned cvta_s(const void* p){
    unsigned r;
    asm("{ .reg .u64 t; cvta.to.shared.u64 t, %1; cvt.u32.u64 %0, t; }" : "=r"(r) : "l"(p));
    return r;
}

// log-depth decay powers: a[k] = (E^(off+2k+1), E^(off+2k+2)), off = sh*8
__device__ __forceinline__ void decays8(float E, int sh, u64 a[4]){
    float E2 = E*E;
    u64 p01 = pk2(E, E2);
    u64 f2  = pk2(E2, E2);
    u64 p23 = mul2(p01, f2);
    float e4 = E2*E2;
    u64 f4  = pk2(e4, e4);
    u64 p45 = mul2(p01, f4);
    u64 p67 = mul2(p23, f4);
    if (sh == 0){ a[0]=p01; a[1]=p23; a[2]=p45; a[3]=p67; }
    else {
        float e8 = e4*e4; u64 f8 = pk2(e8, e8);
        a[0]=mul2(p01,f8); a[1]=mul2(p23,f8); a[2]=mul2(p45,f8); a[3]=mul2(p67,f8);
    }
}

// ---------------- dummy (profiling alignment: makes k2p the 4th launch) ----
__global__ void kdummy(){ if (threadIdx.x == 1024) g_dummy = 0.f; }

// ---------------- K0: fused front weights  Wcat = [W_in@in_proj | W_in] ----
__global__ void k0(const float* __restrict__ Win, const float* __restrict__ bin,
                   const float* __restrict__ inproj){
    int k = blockIdx.x;          // 0..63
    int n = threadIdx.x;         // 0..319
    if (n < 256){
        float acc = 0.f;
        for (int j = 0; j < 64; j++) acc += Win[k*64+j] * inproj[j*256+n];
        g_Wcat[k*320+n] = acc;
        if (k == 0){
            float b = 0.f;
            for (int j = 0; j < 64; j++) b += bin[j] * inproj[j*256+n];
            g_bcat[n] = b;
        }
    } else {
        g_Wcat[k*320+n] = Win[k*64 + (n-256)];
        if (k == 0) g_bcat[n] = bin[n-256];
    }
}

// ---------------- K1: xz = x @ Wcat + bcat -> xc, silu(z), xin --------------
__global__ void __launch_bounds__(256, 3) k1(const float* __restrict__ x){
    extern __shared__ float sm1[];
    float* wS = sm1;               // 64*160
    float* bS = wS + 64*160;       // 160
    float* xT = bS + 160;          // 64*68 (16B-aligned rows)
    int tid = threadIdx.x;
    int nh = blockIdx.x & 1;
    int tg = blockIdx.x >> 1;
    for (int i = tid; i < 64*160; i += 256){
        int k = i/160, n = i%160;
        wS[i] = g_Wcat[k*320 + nh*160 + n];
    }
    for (int i = tid; i < 160; i += 256) bS[i] = g_bcat[nh*160 + i];
    int w = tid >> 5, l = tid & 31;

    for (int tile = tg*2; tile < tg*2 + 2; ++tile){
        __syncthreads();
        for (int i = tid; i < 64*64; i += 256){
            int t = i >> 6, k = i & 63;
            xT[k*68 + t] = x[(tile*64 + t)*64 + k];
        }
        __syncthreads();

        u64 acc[4][5];
        #pragma unroll
        for (int p = 0; p < 4; p++)
            #pragma unroll
            for (int j = 0; j < 5; j++){ float b = bS[l + 32*j]; acc[p][j] = pk2(b, b); }

        #pragma unroll 2
        for (int k = 0; k < 64; k++){
            float4 xa = *(const float4*)&xT[k*68 + w*8 + 0];
            float4 xb = *(const float4*)&xT[k*68 + w*8 + 4];
            u64 xp0 = pk2(xa.x, xa.y);
            u64 xp1 = pk2(xa.z, xa.w);
            u64 xp2 = pk2(xb.x, xb.y);
            u64 xp3 = pk2(xb.z, xb.w);
            #pragma unroll
            for (int j = 0; j < 5; j++){
                float wv = wS[k*160 + l + 32*j];
                u64 w2 = pk2(wv, wv);
                acc[0][j] = fma2(xp0, w2, acc[0][j]);
                acc[1][j] = fma2(xp1, w2, acc[1][j]);
                acc[2][j] = fma2(xp2, w2, acc[2][j]);
                acc[3][j] = fma2(xp3, w2, acc[3][j]);
            }
        }
        #pragma unroll
        for (int p = 0; p < 4; p++){
            int m = tile*64 + w*8 + 2*p;
            #pragma unroll
            for (int j = 0; j < 5; j++){
                float v0, v1; up2(acc[p][j], v0, v1);
                int n = nh*160 + l + 32*j;
                if (n < 128){
                    g_xc[m*128 + n] = v0; g_xc[(m+1)*128 + n] = v1;
                } else if (n < 256){
                    int nn = n - 128;
                    float s0 = v0 * __fdividef(1.f, 1.f + __expf(-v0));
                    float s1 = v1 * __fdividef(1.f, 1.f + __expf(-v1));
                    g_sz[m*128 + nn] = s0; g_sz[(m+1)*128 + nn] = s1;
                } else {
                    g_xin[m*64 + n-256] = v0; g_xin[(m+1)*64 + n-256] = v1;
                }
            }
        }
    }
}

// ---------------- K2': conv + SiLU + x_proj + dt + pack + scan phase 1 ------
// Stage B: 2-token register tiling (threads 0..127), K-packed fma2, no dup MOVs.
__global__ void __launch_bounds__(256) k2p(const float* __restrict__ convw,
                                           const float* __restrict__ convb,
                                           const float* __restrict__ xprojw,
                                           const float* __restrict__ dtw,
                                           const float* __restrict__ dtb,
                                           const float* __restrict__ Alog,
                                           const float* __restrict__ Dskip){
    extern __shared__ float sm2[];
    float* xpT  = sm2;              // 36*130 (even stride: u64-aligned rows)
    float* dtwS = xpT + 36*130;     // 512
    float* cwS  = dtwS + 512;       // 512
    float* dtbS = cwS + 512;        // 128
    float* cbS  = dtbS + 128;       // 128
    float* dskS = cbS + 128;        // 128
    float* uS   = dskS + 128;       // 16*128 (re-used as sdS at the very end)
    float* edS  = uS + 2048;        // 16*128*2 (packed E,du float2)
    float* sB   = edS + 4096;       // 16*16  (16B aligned)
    float* sC   = sB + 256;         // 16*16
    float* dbcS = sC + 256;         // 16*4
    // total = 12808 floats = 51232 B

    int tid = threadIdx.x;
    for (int i = tid; i < 128*36; i += 256){ int dd = i/36, j = i%36; xpT[j*130 + dd] = xprojw[i]; }
    for (int i = tid; i < 512; i += 256){ dtwS[i] = dtw[i]; cwS[i] = convw[i]; }
    if (tid < 128){ dtbS[tid] = dtb[tid]; cbS[tid] = convb[tid]; dskS[tid] = Dskip[tid]; }

    int d  = tid & 127;
    int sh = tid >> 7;
    int b = blockIdx.x >> 6, c = blockIdx.x & 63;
    int base = b*SEQ + c*128;

    float Aval[8]; bool structured = true;
    #pragma unroll
    for (int i = 0; i < 8; i++){
        int s = sh*8 + i;
        Aval[i] = -__expf(Alog[d*16 + s]);
        float kk = (float)(s+1);
        if (fabsf(Aval[i] + kk) > 1e-3f*kk) structured = false;
    }
    u64 h[4]; h[0]=h[1]=h[2]=h[3]=0ull;
    float sdp = 0.f;                 // partial sum of dt (this token-half)
    __syncthreads();

    for (int st = 0; st < 8; ++st){
        int base16 = base + st*16;
        // ---- stage A: conv + silu -> uS (register-reuse over 8 consecutive tokens)
        {
            int gt0 = base16 + sh*8;
            int pos0 = gt0 & (SEQ-1);
            float xv[11];
            #pragma unroll
            for (int i = 0; i < 11; i++)
                xv[i] = (pos0 + i - 3 >= 0) ? g_xc[(gt0 + i - 3)*128 + d] : 0.f;
            float c0 = cwS[d*4+0], c1 = cwS[d*4+1], c2 = cwS[d*4+2], c3 = cwS[d*4+3];
            float cb0 = cbS[d];
            #pragma unroll
            for (int r = 0; r < 8; r++){
                float acc = cb0 + xv[r]*c0 + xv[r+1]*c1 + xv[r+2]*c2 + xv[r+3]*c3;
                float uv = acc * __fdividef(1.f, 1.f + __expf(-acc));
                uS[(sh*8 + r)*128 + d] = uv;
            }
        }
        __syncthreads();
        // ---- stage B: dbc = u @ x_proj  (2-token tile, threads 0..127)
        if (tid < 128){
            int tp = tid >> 4;          // token pair 0..7
            int th = tid & 15;
            int t0 = 2*tp, t1 = t0 + 1;
            const u64* u0 = (const u64*)&uS[t0*128];
            const u64* u1 = (const u64*)&uS[t1*128];
            const u64* x0 = (const u64*)&xpT[ th      *130];
            const u64* x1 = (const u64*)&xpT[(th+16)  *130];
            const u64* x2 = (th < 4) ? (const u64*)&xpT[(th+32)*130] : x0;
            u64 a00=0ull, a01=0ull, a02=0ull, a10=0ull, a11=0ull, a12=0ull;
            #pragma unroll 4
            for (int q = 0; q < 64; q++){
                u64 ua = u0[q], ub = u1[q];
                u64 xa = x0[q], xb = x1[q], xc = x2[q];
                a00 = fma2(ua, xa, a00); a10 = fma2(ub, xa, a10);
                a01 = fma2(ua, xb, a01); a11 = fma2(ub, xb, a11);
                a02 = fma2(ua, xc, a02); a12 = fma2(ub, xc, a12);
            }
            float lo, hi;
            up2(a00, lo, hi); float v00 = lo + hi;
            up2(a01, lo, hi); float v01 = lo + hi;
            up2(a02, lo, hi); float v02 = lo + hi;
            up2(a10, lo, hi); float v10 = lo + hi;
            up2(a11, lo, hi); float v11 = lo + hi;
            up2(a12, lo, hi); float v12 = lo + hi;
            int gt0 = base16 + t0, gt1 = base16 + t1;
            if (th < 4){
                dbcS[t0*4 + th] = v00;
                dbcS[t1*4 + th] = v10;
                sB[t0*16 + th+12] = v01; g_Bm[gt0*16 + th+12] = v01;
                sB[t1*16 + th+12] = v11; g_Bm[gt1*16 + th+12] = v11;
                sC[t0*16 + th+12] = v02; g_Cm[gt0*16 + th+12] = v02;
                sC[t1*16 + th+12] = v12; g_Cm[gt1*16 + th+12] = v12;
            } else {
                sB[t0*16 + th-4] = v00; g_Bm[gt0*16 + th-4] = v00;
                sB[t1*16 + th-4] = v10; g_Bm[gt1*16 + th-4] = v10;
                sC[t0*16 + th-4] = v01; g_Cm[gt0*16 + th-4] = v01;
                sC[t1*16 + th-4] = v11; g_Cm[gt1*16 + th-4] = v11;
            }
        }
        __syncthreads();
        // ---- stage C: dt = softplus(...), E = exp(-dt), pack (E,du) + uu
        #pragma unroll
        for (int r = 0; r < 8; r++){
            int t = sh*8 + r; int gt = base16 + t;
            float xv = dtbS[d];
            #pragma unroll
            for (int rr = 0; rr < 4; rr++) xv += dbcS[t*4 + rr] * dtwS[rr*128 + d];
            float dtv = (xv > 15.f) ? xv : __logf(1.f + __expf(xv));
            float E  = __expf(-dtv);
            float uv = uS[t*128 + d];
            float du = dtv*uv;
            sdp += dtv;
            float2 ed; ed.x = E; ed.y = du;
            *(float2*)&edS[(t*128 + d)*2] = ed;
            g_ed[gt*128 + d] = ed;
            g_uu[gt*128 + d] = uv*dskS[d];
        }
        __syncthreads();
        // ---- stage D: scan 16 steps (phase 1, h from 0 at chunk start)
        const float4* sB4 = (const float4*)sB;
        for (int t = 0; t < 16; t++){
            float2 ed = *(const float2*)&edS[(t*128 + d)*2];
            float E  = ed.x;
            float du = ed.y;
            u64 a[4];
            if (structured){
                decays8(E, sh, a);
            } else {
                float dtv = -__logf(fmaxf(E, 1e-38f));
                #pragma unroll
                for (int k = 0; k < 4; k++)
                    a[k] = pk2(__expf(dtv*Aval[2*k]), __expf(dtv*Aval[2*k+1]));
            }
            u64 du2 = pk2(du, du);
            float4 b0 = sB4[t*4 + sh*2 + 0];
            float4 b1 = sB4[t*4 + sh*2 + 1];
            u64 B0 = f4lo(b0), B1 = f4hi(b0), B2 = f4lo(b1), B3 = f4hi(b1);
            h[0] = fma2(a[0], h[0], mul2(du2, B0));
            h[1] = fma2(a[1], h[1], mul2(du2, B1));
            h[2] = fma2(a[2], h[2], mul2(du2, B2));
            h[3] = fma2(a[3], h[3], mul2(du2, B3));
        }
    }
    int cb = (b*NCHUNK + c)*DI + d;
    u64* Hp = (u64*)&g_Hend[cb*16 + sh*8];
    #pragma unroll
    for (int k = 0; k < 4; k++) Hp[k] = h[k];
    float* sdS = uS;
    sdS[sh*128 + d] = sdp;
    __syncthreads();
    if (sh == 0) g_sd[cb] = sdS[d] + sdS[128 + d];
}

// ---------------- K4: carry scan across chunks (fma-only serial chain) ------
__global__ void __launch_bounds__(256) k4(const float* __restrict__ Alog){
    int tid = blockIdx.x*256 + threadIdx.x;    // 32768 = 16b * 128d * 16s
    int s = tid & 15;
    int d = (tid >> 4) & 127;
    int b = tid >> 11;
    float eA = __expf(Alog[d*16 + s]);          // = -A > 0
    float hc = 0.f;
    #pragma unroll 1
    for (int c0 = 0; c0 < NCHUNK; c0 += 16){
        float sd[16], He[16];
        #pragma unroll
        for (int i = 0; i < 16; i++){
            int cb = (b*NCHUNK + c0 + i)*DI + d;
            sd[i] = g_sd[cb];
            He[i] = g_Hend[cb*16 + s];
        }
        float dec[16];
        #pragma unroll
        for (int i = 0; i < 16; i++) dec[i] = __expf(-eA*sd[i]);
        #pragma unroll
        for (int i = 0; i < 16; i++){
            int cb = (b*NCHUNK + c0 + i)*DI + d;
            g_hini[cb*16 + s] = hc;
            hc = fmaf(dec[i], hc, He[i]);
        }
    }
}

// ---------------- K5: scan phase 3, cp.async double-buffered g_ed stream ----
__global__ void __launch_bounds__(128) k5(const float* __restrict__ Alog){
    extern __shared__ float sm5[];
    float4* sB4 = (float4*)sm5;             // CH*4 float4 = 8192 B
    float4* sC4 = sB4 + CH*4;               // 8192 B
    float2* edb = (float2*)(sC4 + CH*4);    // 2 * 16*128 float2 = 32768 B
    float* sB = (float*)sB4;
    float* sC = (float*)sC4;
    int b = blockIdx.x >> 6, c = blockIdx.x & 63;
    int d = threadIdx.x;
    int base = b*SEQ + c*CH;
    for (int i = d; i < CH*DS; i += 128){ sB[i] = g_Bm[base*16 + i]; sC[i] = g_Cm[base*16 + i]; }
    float Aval[16]; bool structured = true;
    #pragma unroll
    for (int s = 0; s < 16; s++){
        Aval[s] = -__expf(Alog[d*16 + s]);
        float kk = (float)(s+1);
        if (fabsf(Aval[s] + kk) > 1e-3f*kk) structured = false;
    }
    int cb = (b*NCHUNK + c)*DI + d;
    u64 h[8];
    const u64* hp = (const u64*)&g_hini[cb*16];
    #pragma unroll
    for (int k = 0; k < 8; k++) h[k] = hp[k];
    __syncthreads();

    const float2* gp = &g_ed[base*128 + d];
    #pragma unroll
    for (int g = 0; g < 2; g++){
        #pragma unroll
        for (int t = 0; t < 16; t++){
            unsigned sa = cvta_s(edb + g*2048 + t*128 + d);
            asm volatile("cp.async.ca.shared.global [%0], [%1], 8;"
                         :: "r"(sa), "l"(gp + (g*16 + t)*128) : "memory");
        }
        asm volatile("cp.async.commit_group;" ::: "memory");
    }

    for (int g = 0; g < 8; g++){
        asm volatile("cp.async.wait_group 1;" ::: "memory");
        const float2* buf = edb + (g & 1)*2048 + d;
        for (int t = 0; t < 16; t++){
            int T = g*16 + t;
            float2 ed = buf[t*128];
            float E = ed.x, du = ed.y;
            u64 a[8];
            if (structured){
                float E2 = E*E;
                u64 p01 = pk2(E, E2);
                u64 f2  = pk2(E2, E2);
                u64 p23 = mul2(p01, f2);
                float e4 = E2*E2;
                u64 f4v = pk2(e4, e4);
                u64 p45 = mul2(p01, f4v), p67 = mul2(p23, f4v);
                float e8 = e4*e4;
                u64 f8  = pk2(e8, e8);
                a[0]=p01; a[1]=p23; a[2]=p45; a[3]=p67;
                a[4]=mul2(p01,f8); a[5]=mul2(p23,f8); a[6]=mul2(p45,f8); a[7]=mul2(p67,f8);
            } else {
                float dtv = -__logf(fmaxf(E, 1e-38f));
                #pragma unroll
                for (int k = 0; k < 8; k++)
                    a[k] = pk2(__expf(dtv*Aval[2*k]), __expf(dtv*Aval[2*k+1]));
            }
            u64 du2 = pk2(du, du);
            float4 bb0 = sB4[T*4+0], bb1 = sB4[T*4+1], bb2 = sB4[T*4+2], bb3 = sB4[T*4+3];
            float4 cc0 = sC4[T*4+0], cc1 = sC4[T*4+1], cc2 = sC4[T*4+2], cc3 = sC4[T*4+3];
            u64 B[8] = { f4lo(bb0), f4hi(bb0), f4lo(bb1), f4hi(bb1),
                         f4lo(bb2), f4hi(bb2), f4lo(bb3), f4hi(bb3) };
            u64 C[8] = { f4lo(cc0), f4hi(cc0), f4lo(cc1), f4hi(cc1),
                         f4lo(cc2), f4hi(cc2), f4lo(cc3), f4hi(cc3) };
            u64 ya = 0ull, yb = 0ull;
            #pragma unroll
            for (int k = 0; k < 8; k++){
                h[k] = fma2(a[k], h[k], mul2(du2, B[k]));
                if (k & 1) yb = fma2(h[k], C[k], yb);
                else       ya = fma2(h[k], C[k], ya);
            }
            float l0, h0, l1, h1; up2(ya, l0, h0); up2(yb, l1, h1);
            g_yg[(base + T)*128 + d] = (l0 + h0) + (l1 + h1);
        }
        if (g + 2 < 8){
            #pragma unroll
            for (int t = 0; t < 16; t++){
                unsigned sa = cvta_s(edb + (g & 1)*2048 + t*128 + d);
                asm volatile("cp.async.ca.shared.global [%0], [%1], 8;"
                             :: "r"(sa), "l"(gp + ((g+2)*16 + t)*128) : "memory");
            }
        }
        asm volatile("cp.async.commit_group;" ::: "memory");
    }
}

// ---------------- K6: gate + out_proj + residual + layernorm ----------------
__global__ void __launch_bounds__(256) k6(const float* __restrict__ outw,
                                          const float* __restrict__ gamma,
                                          const float* __restrict__ beta,
                                          float* __restrict__ out){
    extern __shared__ float sm6[];
    float* wS = sm6;               // 128*64
    float* yT = wS + 128*64;       // 128*68 (16B-aligned rows)
    __shared__ float gS[64], bS[64];
    int tid = threadIdx.x, w = tid >> 5, l = tid & 31;
    for (int i = tid; i < 128*64; i += 256) wS[i] = outw[i];
    if (tid < 64){ gS[tid] = gamma[tid]; bS[tid] = beta[tid]; }

    for (int tile = blockIdx.x*2; tile < blockIdx.x*2 + 2; ++tile){
        __syncthreads();
        for (int i = tid; i < 64*128; i += 256){
            int t = i >> 7, k = i & 127;
            int idx = (tile*64 + t)*128 + k;
            float yv = g_yg[idx];
            float sz = g_sz[idx];
            float uu = g_uu[idx];
            yT[k*68 + t] = (yv + uu)*sz;
        }
        __syncthreads();
        u64 accA[4], accB[4];
        #pragma unroll
        for (int p = 0; p < 4; p++){ accA[p] = 0ull; accB[p] = 0ull; }
        #pragma unroll 2
        for (int k = 0; k < 128; k++){
            float4 ya = *(const float4*)&yT[k*68 + w*8 + 0];
            float4 yb = *(const float4*)&yT[k*68 + w*8 + 4];
            u64 y0 = pk2(ya.x, ya.y);
            u64 y1 = pk2(ya.z, ya.w);
            u64 y2 = pk2(yb.x, yb.y);
            u64 y3 = pk2(yb.z, yb.w);
            float w0 = wS[k*64 + l], w1 = wS[k*64 + l + 32];
            u64 w02 = pk2(w0, w0), w12 = pk2(w1, w1);
            accA[0] = fma2(y0, w02, accA[0]); accA[1] = fma2(y1, w02, accA[1]);
            accA[2] = fma2(y2, w02, accA[2]); accA[3] = fma2(y3, w02, accA[3]);
            accB[0] = fma2(y0, w12, accB[0]); accB[1] = fma2(y1, w12, accB[1]);
            accB[2] = fma2(y2, w12, accB[2]); accB[3] = fma2(y3, w12, accB[3]);
        }
        #pragma unroll
        for (int p = 0; p < 4; p++){
            int m = tile*64 + w*8 + 2*p;
            float a0, a1, b0, b1;
            up2(accA[p], a0, a1); up2(accB[p], b0, b1);
            float r00 = a0 + g_xin[m*64 + l];
            float r01 = b0 + g_xin[m*64 + l + 32];
            float r10 = a1 + g_xin[(m+1)*64 + l];
            float r11 = b1 + g_xin[(m+1)*64 + l + 32];
            float s0 = r00 + r01, s1 = r10 + r11;
            float q0 = r00*r00 + r01*r01, q1 = r10*r10 + r11*r11;
            #pragma unroll
            for (int o = 16; o; o >>= 1){
                s0 += __shfl_xor_sync(~0u, s0, o);
                s1 += __shfl_xor_sync(~0u, s1, o);
                q0 += __shfl_xor_sync(~0u, q0, o);
                q1 += __shfl_xor_sync(~0u, q1, o);
            }
            float mu0 = s0*(1.f/64.f), mu1 = s1*(1.f/64.f);
            float v0 = q0*(1.f/64.f) - mu0*mu0, v1 = q1*(1.f/64.f) - mu1*mu1;
            float is0 = rsqrtf(v0 + 1e-3f), is1 = rsqrtf(v1 + 1e-3f);
            out[m*64 + l]          = gS[l]      * (r00 - mu0)*is0 + bS[l];
            out[m*64 + l + 32]     = gS[l + 32] * (r01 - mu0)*is0 + bS[l + 32];
            out[(m+1)*64 + l]      = gS[l]      * (r10 - mu1)*is1 + bS[l];
            out[(m+1)*64 + l + 32] = gS[l + 32] * (r11 - mu1)*is1 + bS[l + 32];
        }
    }
}

// ---------------- launch -----------------------------------------------------
extern "C" void kernel_launch(void* const* d_in, const int* in_sizes, int n_in,
                              void* d_out, int out_size){
    const float* x      = (const float*)d_in[0];
    const float* W_in   = (const float*)d_in[1];
    const float* b_in   = (const float*)d_in[2];
    const float* inproj = (const float*)d_in[3];
    const float* convw  = (const float*)d_in[4];
    const float* convb  = (const float*)d_in[5];
    const float* xprojw = (const float*)d_in[6];
    const float* dtw    = (const float*)d_in[7];
    const float* dtb    = (const float*)d_in[8];
    const float* Alog   = (const float*)d_in[9];
    const float* Dskip  = (const float*)d_in[10];
    const float* outw   = (const float*)d_in[11];
    const float* gamma  = (const float*)d_in[12];
    const float* beta   = (const float*)d_in[13];
    float* out = (float*)d_out;

    cudaFuncSetAttribute(k1,  cudaFuncAttributeMaxDynamicSharedMemorySize, 59008);
    cudaFuncSetAttribute(k2p, cudaFuncAttributeMaxDynamicSharedMemorySize, 51232);
    cudaFuncSetAttribute(k5,  cudaFuncAttributeMaxDynamicSharedMemorySize, 49152);
    cudaFuncSetAttribute(k6,  cudaFuncAttributeMaxDynamicSharedMemorySize, 67584);

    kdummy<<<1, 32>>>();
    k0 <<<64, 320>>>(W_in, b_in, inproj);
    k1 <<<2048, 256, 59008>>>(x);
    k2p<<<1024, 256, 51232>>>(convw, convb, xprojw, dtw, dtb, Alog, Dskip);  // 4th -> profiled
    k4 <<<128, 256>>>(Alog);
    k5 <<<1024, 128, 49152>>>(Alog);
    k6 <<<1024, 256, 67584>>>(outw, gamma, beta, out);
}

// round 15
// speedup vs baseline: 1.4456x; 1.4456x over previous
#include <cuda_runtime.h>

#define BATCH 16
#define SEQ   8192
#define BL    (BATCH*SEQ)      // 131072 tokens
#define DM    64
#define DI    128
#define DS    16
#define CH    128              // scan chunk length
#define NCHUNK (SEQ/CH)        // 64

typedef unsigned long long u64;

// ---------------- scratch (device globals; no runtime allocation) ----------
__device__ float  g_xin[BL*DM];
__device__ float  g_xc [BL*DI];
__device__ float  g_sz [BL*DI];          // silu(z)
__device__ float2 g_ed [BL*DI];          // (E, dt*u)
__device__ float  g_uu [BL*DI];          // u * D_skip
__device__ float  g_Bm [BL*DS];
__device__ float  g_Cm [BL*DS];
__device__ float  g_yg [BL*DI];          // raw scan output y
__device__ float  g_Wcat[64*320];
__device__ float  g_bcat[320];
__device__ float  g_sd  [BATCH*NCHUNK*DI];          // sum of dt per chunk
__device__ float  g_Hend[BATCH*NCHUNK*DI*DS];
__device__ float  g_hini[BATCH*NCHUNK*DI*DS];
__device__ float  g_dummy;

// ---------------- packed f32x2 helpers -------------------------------------
__device__ __forceinline__ u64 pk2(float lo, float hi){
    u64 r; asm("mov.b64 %0,{%1,%2};" : "=l"(r) : "f"(lo), "f"(hi)); return r;
}
__device__ __forceinline__ void up2(u64 p, float &lo, float &hi){
    asm("mov.b64 {%0,%1},%2;" : "=f"(lo), "=f"(hi) : "l"(p));
}
__device__ __forceinline__ u64 fma2(u64 a, u64 b, u64 c){
    u64 d; asm("fma.rn.f32x2 %0,%1,%2,%3;" : "=l"(d) : "l"(a), "l"(b), "l"(c)); return d;
}
__device__ __forceinline__ u64 mul2(u64 a, u64 b){
    u64 d; asm("mul.rn.f32x2 %0,%1,%2;" : "=l"(d) : "l"(a), "l"(b)); return d;
}
__device__ __forceinline__ u64 f4lo(float4 v){ return pk2(v.x, v.y); }
__device__ __forceinline__ u64 f4hi(float4 v){ return pk2(v.z, v.w); }
__device__ __forceinline__ unsigned cvta_s(const void* p){
    unsigned r;
    asm("{ .reg .u64 t; cvta.to.shared.u64 t, %1; cvt.u32.u64 %0, t; }" : "=r"(r) : "l"(p));
    return r;
}

// log-depth decay powers: a[k] = (E^(off+2k+1), E^(off+2k+2)), off = sh*8
__device__ __forceinline__ void decays8(float E, int sh, u64 a[4]){
    float E2 = E*E;
    u64 p01 = pk2(E, E2);
    u64 f2  = pk2(E2, E2);
    u64 p23 = mul2(p01, f2);
    float e4 = E2*E2;
    u64 f4  = pk2(e4, e4);
    u64 p45 = mul2(p01, f4);
    u64 p67 = mul2(p23, f4);
    if (sh == 0){ a[0]=p01; a[1]=p23; a[2]=p45; a[3]=p67; }
    else {
        float e8 = e4*e4; u64 f8 = pk2(e8, e8);
        a[0]=mul2(p01,f8); a[1]=mul2(p23,f8); a[2]=mul2(p45,f8); a[3]=mul2(p67,f8);
    }
}

// ---------------- dummy (profiling alignment: makes k2p the 4th launch) ----
__global__ void kdummy(){ if (threadIdx.x == 1024) g_dummy = 0.f; }

// ---------------- K0: fused front weights  Wcat = [W_in@in_proj | W_in] ----
__global__ void k0(const float* __restrict__ Win, const float* __restrict__ bin,
                   const float* __restrict__ inproj){
    int k = blockIdx.x;          // 0..63
    int n = threadIdx.x;         // 0..319
    if (n < 256){
        float acc = 0.f;
        for (int j = 0; j < 64; j++) acc += Win[k*64+j] * inproj[j*256+n];
        g_Wcat[k*320+n] = acc;
        if (k == 0){
            float b = 0.f;
            for (int j = 0; j < 64; j++) b += bin[j] * inproj[j*256+n];
            g_bcat[n] = b;
        }
    } else {
        g_Wcat[k*320+n] = Win[k*64 + (n-256)];
        if (k == 0) g_bcat[n] = bin[n-256];
    }
}

// ---------------- K1: xz = x @ Wcat + bcat -> xc, silu(z), xin --------------
__global__ void __launch_bounds__(256, 3) k1(const float* __restrict__ x){
    extern __shared__ float sm1[];
    float* wS = sm1;               // 64*160
    float* bS = wS + 64*160;       // 160
    float* xT = bS + 160;          // 64*68 (16B-aligned rows)
    int tid = threadIdx.x;
    int nh = blockIdx.x & 1;
    int tg = blockIdx.x >> 1;
    for (int i = tid; i < 64*160; i += 256){
        int k = i/160, n = i%160;
        wS[i] = g_Wcat[k*320 + nh*160 + n];
    }
    for (int i = tid; i < 160; i += 256) bS[i] = g_bcat[nh*160 + i];
    int w = tid >> 5, l = tid & 31;

    for (int tile = tg*2; tile < tg*2 + 2; ++tile){
        __syncthreads();
        for (int i = tid; i < 64*64; i += 256){
            int t = i >> 6, k = i & 63;
            xT[k*68 + t] = x[(tile*64 + t)*64 + k];
        }
        __syncthreads();

        u64 acc[4][5];
        #pragma unroll
        for (int p = 0; p < 4; p++)
            #pragma unroll
            for (int j = 0; j < 5; j++){ float b = bS[l + 32*j]; acc[p][j] = pk2(b, b); }

        #pragma unroll 2
        for (int k = 0; k < 64; k++){
            float4 xa = *(const float4*)&xT[k*68 + w*8 + 0];
            float4 xb = *(const float4*)&xT[k*68 + w*8 + 4];
            u64 xp0 = pk2(xa.x, xa.y);
            u64 xp1 = pk2(xa.z, xa.w);
            u64 xp2 = pk2(xb.x, xb.y);
            u64 xp3 = pk2(xb.z, xb.w);
            #pragma unroll
            for (int j = 0; j < 5; j++){
                float wv = wS[k*160 + l + 32*j];
                u64 w2 = pk2(wv, wv);
                acc[0][j] = fma2(xp0, w2, acc[0][j]);
                acc[1][j] = fma2(xp1, w2, acc[1][j]);
                acc[2][j] = fma2(xp2, w2, acc[2][j]);
                acc[3][j] = fma2(xp3, w2, acc[3][j]);
            }
        }
        #pragma unroll
        for (int p = 0; p < 4; p++){
            int m = tile*64 + w*8 + 2*p;
            #pragma unroll
            for (int j = 0; j < 5; j++){
                float v0, v1; up2(acc[p][j], v0, v1);
                int n = nh*160 + l + 32*j;
                if (n < 128){
                    g_xc[m*128 + n] = v0; g_xc[(m+1)*128 + n] = v1;
                } else if (n < 256){
                    int nn = n - 128;
                    float s0 = v0 * __fdividef(1.f, 1.f + __expf(-v0));
                    float s1 = v1 * __fdividef(1.f, 1.f + __expf(-v1));
                    g_sz[m*128 + nn] = s0; g_sz[(m+1)*128 + nn] = s1;
                } else {
                    g_xin[m*64 + n-256] = v0; g_xin[(m+1)*64 + n-256] = v1;
                }
            }
        }
    }
}

// ---------------- K2': conv + SiLU + x_proj + dt + pack + scan phase 1 ------
// (round-13 / round-8 stage B: 16 tokens x 16 threads, u64 dot products)
__global__ void __launch_bounds__(256) k2p(const float* __restrict__ convw,
                                           const float* __restrict__ convb,
                                           const float* __restrict__ xprojw,
                                           const float* __restrict__ dtw,
                                           const float* __restrict__ dtb,
                                           const float* __restrict__ Alog,
                                           const float* __restrict__ Dskip){
    extern __shared__ float sm2[];
    float* xpT  = sm2;              // 36*130 (even stride: u64-aligned rows)
    float* dtwS = xpT + 36*130;     // 512
    float* cwS  = dtwS + 512;       // 512
    float* dtbS = cwS + 512;        // 128
    float* cbS  = dtbS + 128;       // 128
    float* dskS = cbS + 128;        // 128
    float* uS   = dskS + 128;       // 16*128 (re-used as sdS at the very end)
    float* edS  = uS + 2048;        // 16*128*2 (packed E,du float2)
    float* sB   = edS + 4096;       // 16*16  (16B aligned)
    float* sC   = sB + 256;         // 16*16
    float* dbcS = sC + 256;         // 16*4
    // total = 12808 floats = 51232 B

    int tid = threadIdx.x;
    for (int i = tid; i < 128*36; i += 256){ int dd = i/36, j = i%36; xpT[j*130 + dd] = xprojw[i]; }
    for (int i = tid; i < 512; i += 256){ dtwS[i] = dtw[i]; cwS[i] = convw[i]; }
    if (tid < 128){ dtbS[tid] = dtb[tid]; cbS[tid] = convb[tid]; dskS[tid] = Dskip[tid]; }

    int d  = tid & 127;
    int sh = tid >> 7;
    int b = blockIdx.x >> 6, c = blockIdx.x & 63;
    int base = b*SEQ + c*128;

    float Aval[8]; bool structured = true;
    #pragma unroll
    for (int i = 0; i < 8; i++){
        int s = sh*8 + i;
        Aval[i] = -__expf(Alog[d*16 + s]);
        float kk = (float)(s+1);
        if (fabsf(Aval[i] + kk) > 1e-3f*kk) structured = false;
    }
    u64 h[4]; h[0]=h[1]=h[2]=h[3]=0ull;
    float sdp = 0.f;                 // partial sum of dt (this token-half)
    __syncthreads();

    for (int st = 0; st < 8; ++st){
        int base16 = base + st*16;
        // ---- stage A: conv + silu -> uS (register-reuse over 8 consecutive tokens)
        {
            int gt0 = base16 + sh*8;
            int pos0 = gt0 & (SEQ-1);
            float xv[11];
            #pragma unroll
            for (int i = 0; i < 11; i++)
                xv[i] = (pos0 + i - 3 >= 0) ? g_xc[(gt0 + i - 3)*128 + d] : 0.f;
            float c0 = cwS[d*4+0], c1 = cwS[d*4+1], c2 = cwS[d*4+2], c3 = cwS[d*4+3];
            float cb0 = cbS[d];
            #pragma unroll
            for (int r = 0; r < 8; r++){
                float acc = cb0 + xv[r]*c0 + xv[r+1]*c1 + xv[r+2]*c2 + xv[r+3]*c3;
                float uv = acc * __fdividef(1.f, 1.f + __expf(-acc));
                uS[(sh*8 + r)*128 + d] = uv;
            }
        }
        __syncthreads();
        // ---- stage B: dbc = u @ x_proj
        {
            int t  = tid >> 4;
            int th = tid & 15;
            const u64* up = (const u64*)&uS[t*128];
            const u64* x0 = (const u64*)&xpT[ th      *130];
            const u64* x1 = (const u64*)&xpT[(th+16)  *130];
            const u64* x2 = (th < 4) ? (const u64*)&xpT[(th+32)*130] : x0;
            u64 a0 = 0ull, a1 = 0ull, a2 = 0ull;
            #pragma unroll 4
            for (int q = 0; q < 64; q++){
                u64 uv2 = up[q];
                a0 = fma2(uv2, x0[q], a0);
                a1 = fma2(uv2, x1[q], a1);
                a2 = fma2(uv2, x2[q], a2);
            }
            float lo, hi;
            up2(a0, lo, hi); float v0 = lo + hi;
            up2(a1, lo, hi); float v1 = lo + hi;
            up2(a2, lo, hi); float v2 = lo + hi;
            int gt = base16 + t;
            if (th < 4) dbcS[t*4 + th] = v0;
            else { sB[t*16 + th-4]  = v0; g_Bm[gt*16 + th-4]  = v0; }
            if (th < 4){ sB[t*16 + th+12] = v1; g_Bm[gt*16 + th+12] = v1; }
            else { sC[t*16 + th-4] = v1; g_Cm[gt*16 + th-4] = v1; }
            if (th < 4){ sC[t*16 + th+12] = v2; g_Cm[gt*16 + th+12] = v2; }
        }
        __syncthreads();
        // ---- stage C: dt = softplus(...), E = exp(-dt), pack (E,du) + uu
        #pragma unroll
        for (int r = 0; r < 8; r++){
            int t = sh*8 + r; int gt = base16 + t;
            float xv = dtbS[d];
            #pragma unroll
            for (int rr = 0; rr < 4; rr++) xv += dbcS[t*4 + rr] * dtwS[rr*128 + d];
            float dtv = (xv > 15.f) ? xv : __logf(1.f + __expf(xv));
            float E  = __expf(-dtv);
            float uv = uS[t*128 + d];
            float du = dtv*uv;
            sdp += dtv;
            float2 ed; ed.x = E; ed.y = du;
            *(float2*)&edS[(t*128 + d)*2] = ed;
            g_ed[gt*128 + d] = ed;
            g_uu[gt*128 + d] = uv*dskS[d];
        }
        __syncthreads();
        // ---- stage D: scan 16 steps (phase 1, h from 0 at chunk start)
        const float4* sB4 = (const float4*)sB;
        for (int t = 0; t < 16; t++){
            float2 ed = *(const float2*)&edS[(t*128 + d)*2];
            float E  = ed.x;
            float du = ed.y;
            u64 a[4];
            if (structured){
                decays8(E, sh, a);
            } else {
                float dtv = -__logf(fmaxf(E, 1e-38f));
                #pragma unroll
                for (int k = 0; k < 4; k++)
                    a[k] = pk2(__expf(dtv*Aval[2*k]), __expf(dtv*Aval[2*k+1]));
            }
            u64 du2 = pk2(du, du);
            float4 b0 = sB4[t*4 + sh*2 + 0];
            float4 b1 = sB4[t*4 + sh*2 + 1];
            u64 B0 = f4lo(b0), B1 = f4hi(b0), B2 = f4lo(b1), B3 = f4hi(b1);
            h[0] = fma2(a[0], h[0], mul2(du2, B0));
            h[1] = fma2(a[1], h[1], mul2(du2, B1));
            h[2] = fma2(a[2], h[2], mul2(du2, B2));
            h[3] = fma2(a[3], h[3], mul2(du2, B3));
        }
    }
    int cb = (b*NCHUNK + c)*DI + d;
    u64* Hp = (u64*)&g_Hend[cb*16 + sh*8];
    #pragma unroll
    for (int k = 0; k < 4; k++) Hp[k] = h[k];
    float* sdS = uS;
    sdS[sh*128 + d] = sdp;
    __syncthreads();
    if (sh == 0) g_sd[cb] = sdS[d] + sdS[128 + d];
}

// ---------------- K4: carry scan across chunks (fma-only serial chain) ------
__global__ void __launch_bounds__(256) k4(const float* __restrict__ Alog){
    int tid = blockIdx.x*256 + threadIdx.x;    // 32768 = 16b * 128d * 16s
    int s = tid & 15;
    int d = (tid >> 4) & 127;
    int b = tid >> 11;
    float eA = __expf(Alog[d*16 + s]);          // = -A > 0
    float hc = 0.f;
    #pragma unroll 1
    for (int c0 = 0; c0 < NCHUNK; c0 += 16){
        float sd[16], He[16];
        #pragma unroll
        for (int i = 0; i < 16; i++){
            int cb = (b*NCHUNK + c0 + i)*DI + d;
            sd[i] = g_sd[cb];
            He[i] = g_Hend[cb*16 + s];
        }
        float dec[16];
        #pragma unroll
        for (int i = 0; i < 16; i++) dec[i] = __expf(-eA*sd[i]);
        #pragma unroll
        for (int i = 0; i < 16; i++){
            int cb = (b*NCHUNK + c0 + i)*DI + d;
            g_hini[cb*16 + s] = hc;
            hc = fmaf(dec[i], hc, He[i]);
        }
    }
}

// ---------------- K5: scan phase 3, cp.async double-buffered g_ed stream ----
// B/C tiles also loaded via an early cp.async group (overlapped with preamble).
__global__ void __launch_bounds__(128) k5(const float* __restrict__ Alog){
    extern __shared__ float sm5[];
    float4* sB4 = (float4*)sm5;             // CH*4 float4 = 8192 B
    float4* sC4 = sB4 + CH*4;               // 8192 B
    float2* edb = (float2*)(sC4 + CH*4);    // 2 * 16*128 float2 = 32768 B
    int b = blockIdx.x >> 6, c = blockIdx.x & 63;
    int d = threadIdx.x;
    int base = b*SEQ + c*CH;

    // early group: B/C tiles via cp.async (4 float4 per thread per array)
    {
        const float4* gB = (const float4*)&g_Bm[base*16];
        const float4* gC = (const float4*)&g_Cm[base*16];
        #pragma unroll
        for (int j = 0; j < 4; j++){
            int f = d + 128*j;
            unsigned sa = cvta_s(&sB4[f]);
            asm volatile("cp.async.ca.shared.global [%0], [%1], 16;"
                         :: "r"(sa), "l"(gB + f) : "memory");
            unsigned sc = cvta_s(&sC4[f]);
            asm volatile("cp.async.ca.shared.global [%0], [%1], 16;"
                         :: "r"(sc), "l"(gC + f) : "memory");
        }
        asm volatile("cp.async.commit_group;" ::: "memory");
    }

    float Aval[16]; bool structured = true;
    #pragma unroll
    for (int s = 0; s < 16; s++){
        Aval[s] = -__expf(Alog[d*16 + s]);
        float kk = (float)(s+1);
        if (fabsf(Aval[s] + kk) > 1e-3f*kk) structured = false;
    }
    int cb = (b*NCHUNK + c)*DI + d;
    u64 h[8];
    const u64* hp = (const u64*)&g_hini[cb*16];
    #pragma unroll
    for (int k = 0; k < 8; k++) h[k] = hp[k];

    const float2* gp = &g_ed[base*128 + d];
    #pragma unroll
    for (int g = 0; g < 2; g++){
        #pragma unroll
        for (int t = 0; t < 16; t++){
            unsigned sa = cvta_s(edb + g*2048 + t*128 + d);
            asm volatile("cp.async.ca.shared.global [%0], [%1], 8;"
                         :: "r"(sa), "l"(gp + (g*16 + t)*128) : "memory");
        }
        asm volatile("cp.async.commit_group;" ::: "memory");
    }
    // drain the B/C group (allow the 2 ed groups to stay in flight)
    asm volatile("cp.async.wait_group 2;" ::: "memory");
    __syncthreads();

    for (int g = 0; g < 8; g++){
        asm volatile("cp.async.wait_group 1;" ::: "memory");
        const float2* buf = edb + (g & 1)*2048 + d;
        for (int t = 0; t < 16; t++){
            int T = g*16 + t;
            float2 ed = buf[t*128];
            float E = ed.x, du = ed.y;
            u64 a[8];
            if (structured){
                float E2 = E*E;
                u64 p01 = pk2(E, E2);
                u64 f2  = pk2(E2, E2);
                u64 p23 = mul2(p01, f2);
                float e4 = E2*E2;
                u64 f4v = pk2(e4, e4);
                u64 p45 = mul2(p01, f4v), p67 = mul2(p23, f4v);
                float e8 = e4*e4;
                u64 f8  = pk2(e8, e8);
                a[0]=p01; a[1]=p23; a[2]=p45; a[3]=p67;
                a[4]=mul2(p01,f8); a[5]=mul2(p23,f8); a[6]=mul2(p45,f8); a[7]=mul2(p67,f8);
            } else {
                float dtv = -__logf(fmaxf(E, 1e-38f));
                #pragma unroll
                for (int k = 0; k < 8; k++)
                    a[k] = pk2(__expf(dtv*Aval[2*k]), __expf(dtv*Aval[2*k+1]));
            }
            u64 du2 = pk2(du, du);
            float4 bb0 = sB4[T*4+0], bb1 = sB4[T*4+1], bb2 = sB4[T*4+2], bb3 = sB4[T*4+3];
            float4 cc0 = sC4[T*4+0], cc1 = sC4[T*4+1], cc2 = sC4[T*4+2], cc3 = sC4[T*4+3];
            u64 B[8] = { f4lo(bb0), f4hi(bb0), f4lo(bb1), f4hi(bb1),
                         f4lo(bb2), f4hi(bb2), f4lo(bb3), f4hi(bb3) };
            u64 C[8] = { f4lo(cc0), f4hi(cc0), f4lo(cc1), f4hi(cc1),
                         f4lo(cc2), f4hi(cc2), f4lo(cc3), f4hi(cc3) };
            u64 ya = 0ull, yb = 0ull;
            #pragma unroll
            for (int k = 0; k < 8; k++){
                h[k] = fma2(a[k], h[k], mul2(du2, B[k]));
                if (k & 1) yb = fma2(h[k], C[k], yb);
                else       ya = fma2(h[k], C[k], ya);
            }
            float l0, h0, l1, h1; up2(ya, l0, h0); up2(yb, l1, h1);
            g_yg[(base + T)*128 + d] = (l0 + h0) + (l1 + h1);
        }
        if (g + 2 < 8){
            #pragma unroll
            for (int t = 0; t < 16; t++){
                unsigned sa = cvta_s(edb + (g & 1)*2048 + t*128 + d);
                asm volatile("cp.async.ca.shared.global [%0], [%1], 8;"
                             :: "r"(sa), "l"(gp + ((g+2)*16 + t)*128) : "memory");
            }
        }
        asm volatile("cp.async.commit_group;" ::: "memory");
    }
}

// ---------------- K6: gate + out_proj + residual + layernorm ----------------
__global__ void __launch_bounds__(256) k6(const float* __restrict__ outw,
                                          const float* __restrict__ gamma,
                                          const float* __restrict__ beta,
                                          float* __restrict__ out){
    extern __shared__ float sm6[];
    float* wS = sm6;               // 128*64
    float* yT = wS + 128*64;       // 128*68 (16B-aligned rows)
    __shared__ float gS[64], bS[64];
    int tid = threadIdx.x, w = tid >> 5, l = tid & 31;
    for (int i = tid; i < 128*64; i += 256) wS[i] = outw[i];
    if (tid < 64){ gS[tid] = gamma[tid]; bS[tid] = beta[tid]; }

    for (int tile = blockIdx.x*2; tile < blockIdx.x*2 + 2; ++tile){
        __syncthreads();
        for (int i = tid; i < 64*128; i += 256){
            int t = i >> 7, k = i & 127;
            int idx = (tile*64 + t)*128 + k;
            float yv = g_yg[idx];
            float sz = g_sz[idx];
            float uu = g_uu[idx];
            yT[k*68 + t] = (yv + uu)*sz;
        }
        __syncthreads();
        u64 accA[4], accB[4];
        #pragma unroll
        for (int p = 0; p < 4; p++){ accA[p] = 0ull; accB[p] = 0ull; }
        #pragma unroll 2
        for (int k = 0; k < 128; k++){
            float4 ya = *(const float4*)&yT[k*68 + w*8 + 0];
            float4 yb = *(const float4*)&yT[k*68 + w*8 + 4];
            u64 y0 = pk2(ya.x, ya.y);
            u64 y1 = pk2(ya.z, ya.w);
            u64 y2 = pk2(yb.x, yb.y);
            u64 y3 = pk2(yb.z, yb.w);
            float w0 = wS[k*64 + l], w1 = wS[k*64 + l + 32];
            u64 w02 = pk2(w0, w0), w12 = pk2(w1, w1);
            accA[0] = fma2(y0, w02, accA[0]); accA[1] = fma2(y1, w02, accA[1]);
            accA[2] = fma2(y2, w02, accA[2]); accA[3] = fma2(y3, w02, accA[3]);
            accB[0] = fma2(y0, w12, accB[0]); accB[1] = fma2(y1, w12, accB[1]);
            accB[2] = fma2(y2, w12, accB[2]); accB[3] = fma2(y3, w12, accB[3]);
        }
        #pragma unroll
        for (int p = 0; p < 4; p++){
            int m = tile*64 + w*8 + 2*p;
            float a0, a1, b0, b1;
            up2(accA[p], a0, a1); up2(accB[p], b0, b1);
            float r00 = a0 + g_xin[m*64 + l];
            float r01 = b0 + g_xin[m*64 + l + 32];
            float r10 = a1 + g_xin[(m+1)*64 + l];
            float r11 = b1 + g_xin[(m+1)*64 + l + 32];
            float s0 = r00 + r01, s1 = r10 + r11;
            float q0 = r00*r00 + r01*r01, q1 = r10*r10 + r11*r11;
            #pragma unroll
            for (int o = 16; o; o >>= 1){
                s0 += __shfl_xor_sync(~0u, s0, o);
                s1 += __shfl_xor_sync(~0u, s1, o);
                q0 += __shfl_xor_sync(~0u, q0, o);
                q1 += __shfl_xor_sync(~0u, q1, o);
            }
            float mu0 = s0*(1.f/64.f), mu1 = s1*(1.f/64.f);
            float v0 = q0*(1.f/64.f) - mu0*mu0, v1 = q1*(1.f/64.f) - mu1*mu1;
            float is0 = rsqrtf(v0 + 1e-3f), is1 = rsqrtf(v1 + 1e-3f);
            out[m*64 + l]          = gS[l]      * (r00 - mu0)*is0 + bS[l];
            out[m*64 + l + 32]     = gS[l + 32] * (r01 - mu0)*is0 + bS[l + 32];
            out[(m+1)*64 + l]      = gS[l]      * (r10 - mu1)*is1 + bS[l];
            out[(m+1)*64 + l + 32] = gS[l + 32] * (r11 - mu1)*is1 + bS[l + 32];
        }
    }
}

// ---------------- launch -----------------------------------------------------
extern "C" void kernel_launch(void* const* d_in, const int* in_sizes, int n_in,
                              void* d_out, int out_size){
    const float* x      = (const float*)d_in[0];
    const float* W_in   = (const float*)d_in[1];
    const float* b_in   = (const float*)d_in[2];
    const float* inproj = (const float*)d_in[3];
    const float* convw  = (const float*)d_in[4];
    const float* convb  = (const float*)d_in[5];
    const float* xprojw = (const float*)d_in[6];
    const float* dtw    = (const float*)d_in[7];
    const float* dtb    = (const float*)d_in[8];
    const float* Alog   = (const float*)d_in[9];
    const float* Dskip  = (const float*)d_in[10];
    const float* outw   = (const float*)d_in[11];
    const float* gamma  = (const float*)d_in[12];
    const float* beta   = (const float*)d_in[13];
    float* out = (float*)d_out;

    cudaFuncSetAttribute(k1,  cudaFuncAttributeMaxDynamicSharedMemorySize, 59008);
    cudaFuncSetAttribute(k2p, cudaFuncAttributeMaxDynamicSharedMemorySize, 51232);
    cudaFuncSetAttribute(k5,  cudaFuncAttributeMaxDynamicSharedMemorySize, 49152);
    cudaFuncSetAttribute(k6,  cudaFuncAttributeMaxDynamicSharedMemorySize, 67584);

    kdummy<<<1, 32>>>();
    k0 <<<64, 320>>>(W_in, b_in, inproj);
    k1 <<<2048, 256, 59008>>>(x);
    k2p<<<1024, 256, 51232>>>(convw, convb, xprojw, dtw, dtb, Alog, Dskip);  // 4th -> profiled
    k4 <<<128, 256>>>(Alog);
    k5 <<<1024, 128, 49152>>>(Alog);
    k6 <<<1024, 256, 67584>>>(outw, gamma, beta, out);
}